// round 12
// baseline (speedup 1.0000x reference)
#include <cuda_runtime.h>
#include <cuda_fp16.h>
#include <cstdint>
#include <cstddef>

#define EPSV 1e-5f

// g_q/g_k: fp16 [(s*32+c)*256 + b] — GEMM1 operand rows, K(=b)-contiguous
__device__ __half g_q[384 * 32 * 256];
__device__ __half g_k[384 * 32 * 256];
// g_wo: fp16, 16 k-chunks, each preswizzled smem image [n=128][64 halfs]
__device__ __half g_wo[16 * 128 * 64];
// g_a: fp16 [p = i*384+j][e = c*32+d] row-major — GEMM2 A operand (302 MB)
__device__ __half g_a[150994944];

// ---------------- helpers ----------------
__device__ __forceinline__ uint32_t smem_u32(const void* p) {
    uint32_t a;
    asm("{ .reg .u64 t; cvta.to.shared.u64 t, %1; cvt.u32.u64 %0, t; }" : "=r"(a) : "l"(p));
    return a;
}
#define CP_ASYNC16(dst, src) \
    asm volatile("cp.async.cg.shared.global [%0], [%1], 16;" :: "r"(dst), "l"(src))
#define CP_COMMIT() asm volatile("cp.async.commit_group;")
#define CP_WAIT1()  asm volatile("cp.async.wait_group 1;")
#define CP_WAIT0()  asm volatile("cp.async.wait_group 0;")

#define LDSM_X4(r0, r1, r2, r3, addr) \
    asm volatile("ldmatrix.sync.aligned.m8n8.x4.shared.b16 {%0,%1,%2,%3}, [%4];" \
                 : "=r"(r0), "=r"(r1), "=r"(r2), "=r"(r3) : "r"(addr))

__device__ __forceinline__ void mma_f16(float* d, uint32_t a0, uint32_t a1,
                                        uint32_t a2, uint32_t a3,
                                        uint32_t b0, uint32_t b1) {
    asm volatile(
        "mma.sync.aligned.m16n8k16.row.col.f32.f16.f16.f32 "
        "{%0,%1,%2,%3}, {%4,%5,%6,%7}, {%8,%9}, {%0,%1,%2,%3};"
        : "+f"(d[0]), "+f"(d[1]), "+f"(d[2]), "+f"(d[3])
        : "r"(a0), "r"(a1), "r"(a2), "r"(a3), "r"(b0), "r"(b1));
}

// ============================================================================
// proj: rmsnorm(m)*g_in -> q/k projections -> fp16 transposed store
// ============================================================================
__global__ __launch_bounds__(256, 2)
void proj_kernel(const float* __restrict__ m, const float* __restrict__ g_in,
                 const float* __restrict__ Wq, const float* __restrict__ bq,
                 const float* __restrict__ Wk, const float* __restrict__ bk)
{
    extern __shared__ float sm[];
    float* Wq_s = sm;
    float* Wk_s = sm + 8192;
    float* mn_s = sm + 16384;
    const int tid = threadIdx.x, warp = tid >> 5, lane = tid & 31;
    const float4* Wq4 = (const float4*)Wq;
    const float4* Wk4 = (const float4*)Wk;
#pragma unroll
    for (int v = 0; v < 8; ++v) {
        ((float4*)Wq_s)[v * 256 + tid] = Wq4[v * 256 + tid];
        ((float4*)Wk_s)[v * 256 + tid] = Wk4[v * 256 + tid];
    }
    const int rb = (blockIdx.x * 8 + warp) * 4;
    float* mw = mn_s + warp * 1024;
    const float4 gi0 = ((const float4*)g_in)[lane * 2];
    const float4 gi1 = ((const float4*)g_in)[lane * 2 + 1];
    float vals[4][8], ssum[4];
#pragma unroll
    for (int r = 0; r < 4; ++r) {
        const float4* mp = (const float4*)(m + (size_t)(rb + r) * 256);
        float4 a = mp[lane * 2], b = mp[lane * 2 + 1];
        vals[r][0] = a.x; vals[r][1] = a.y; vals[r][2] = a.z; vals[r][3] = a.w;
        vals[r][4] = b.x; vals[r][5] = b.y; vals[r][6] = b.z; vals[r][7] = b.w;
        ssum[r] = a.x*a.x + a.y*a.y + a.z*a.z + a.w*a.w
                + b.x*b.x + b.y*b.y + b.z*b.z + b.w*b.w;
    }
#pragma unroll
    for (int r = 0; r < 4; ++r) {
        float s = ssum[r];
#pragma unroll
        for (int o = 16; o >= 1; o >>= 1) s += __shfl_xor_sync(~0u, s, o);
        const float sc = rsqrtf(s * (1.0f / 256.0f) + EPSV);
        float4 o0, o1;
        o0.x = vals[r][0]*sc*gi0.x; o0.y = vals[r][1]*sc*gi0.y;
        o0.z = vals[r][2]*sc*gi0.z; o0.w = vals[r][3]*sc*gi0.w;
        o1.x = vals[r][4]*sc*gi1.x; o1.y = vals[r][5]*sc*gi1.y;
        o1.z = vals[r][6]*sc*gi1.z; o1.w = vals[r][7]*sc*gi1.w;
        ((float4*)(mw + r * 256))[lane * 2]     = o0;
        ((float4*)(mw + r * 256))[lane * 2 + 1] = o1;
    }
    __syncthreads();
    float aq[4], ak[4];
    const float bqv = __ldg(bq + lane), bkv = __ldg(bk + lane);
#pragma unroll
    for (int r = 0; r < 4; ++r) { aq[r] = bqv; ak[r] = bkv; }
#pragma unroll 4
    for (int mm = 0; mm < 256; ++mm) {
        const float wq = Wq_s[mm * 32 + lane], wk = Wk_s[mm * 32 + lane];
#pragma unroll
        for (int r = 0; r < 4; ++r) {
            const float x = mw[r * 256 + mm];
            aq[r] = fmaf(x, wq, aq[r]);
            ak[r] = fmaf(x, wk, ak[r]);
        }
    }
#pragma unroll
    for (int r = 0; r < 4; ++r) {
        const int row = rb + r, b = row / 384, s = row - b * 384;
        g_q[(size_t)(s * 32 + lane) * 256 + b] = __float2half(aq[r]);
        g_k[(size_t)(s * 32 + lane) * 256 + b] = __float2half(ak[r]);
    }
}

// ============================================================================
// wot: Wo[e=ks*64+kk][z=n] -> g_wo[ks][n*64 + swz(kk,n)]  (fp16)
// ============================================================================
__global__ void wot_kernel(const float* __restrict__ Wo) {
    const int ks = blockIdx.x, n = threadIdx.x;
    __half* dst = g_wo + ks * 8192 + n * 64;
    const int n7 = n & 7;
#pragma unroll
    for (int kk = 0; kk < 64; ++kk) {
        const float v = __ldg(Wo + (size_t)(ks * 64 + kk) * 128 + n);
        dst[(((kk >> 3) ^ n7) << 3) | (kk & 7)] = __float2half(v);
    }
}

// ============================================================================
// gemm1: 128 thr, 4 warps 2x2, warp tile 64x64, fp16 m16n8k16, 3 CTAs/SM.
// 128x128 tile, K=256 in 4 chunks of 64; 2-stage ring; direct scatter.
// ============================================================================
__global__ __launch_bounds__(128, 3)
void gemm1_kernel() {
    extern __shared__ float sm[];
    const int tid = threadIdx.x, w = tid >> 5, l = tid & 31;
    const int mw = w >> 1, nw = w & 1, lg = l >> 2, lm4 = l & 3;
    const int irow = blockIdx.y * 128, jrow = blockIdx.x * 128;
    const uint32_t smb = smem_u32(sm);

    const int r7 = l & 7;
    const int rhiA = (l >> 3) & 1, kbA = (l >> 4) & 1;
    const int rhiB = (l >> 4) & 1, kbB = (l >> 3) & 1;
    uint32_t aRow[4], bRow[4];
#pragma unroll
    for (int mi = 0; mi < 4; ++mi)
        aRow[mi] = (uint32_t)((mw * 64 + mi * 16 + rhiA * 8 + r7) * 128);
#pragma unroll
    for (int nip = 0; nip < 4; ++nip)
        bRow[nip] = (uint32_t)(16384 + (nw * 64 + nip * 16 + rhiB * 8 + r7) * 128);

    float acc[4][8][4] = {};

    int srow[8], sq[8];
    uint32_t sdst[8];
#pragma unroll
    for (int v = 0; v < 8; ++v) {
        const int fl = v * 128 + tid;
        srow[v] = fl >> 3;
        sq[v]   = fl & 7;
        sdst[v] = (uint32_t)((srow[v] * 8 + (sq[v] ^ (srow[v] & 7))) * 16);
    }

#define G1_STAGE(ks, buf) do {                                                  \
    const uint32_t bofs = smb + (uint32_t)(buf) * 32768u;                       \
    _Pragma("unroll")                                                           \
    for (int v = 0; v < 8; ++v) {                                               \
        const __half* sA = g_q + (size_t)(irow + srow[v]) * 256 + (ks) * 64 + sq[v] * 8; \
        const __half* sB = g_k + (size_t)(jrow + srow[v]) * 256 + (ks) * 64 + sq[v] * 8; \
        CP_ASYNC16(bofs + sdst[v], sA);                                         \
        CP_ASYNC16(bofs + 16384 + sdst[v], sB);                                 \
    }                                                                           \
    CP_COMMIT();                                                                \
} while (0)

    G1_STAGE(0, 0);
#pragma unroll
    for (int ks = 0; ks < 4; ++ks) {
        if (ks + 1 < 4) { G1_STAGE(ks + 1, (ks + 1) & 1); CP_WAIT1(); }
        else            { CP_WAIT0(); }
        __syncthreads();
        const uint32_t stage = smb + (uint32_t)(ks & 1) * 32768u;
#pragma unroll
        for (int s = 0; s < 4; ++s) {
            const uint32_t uA = (uint32_t)((((s << 1) | kbA) ^ r7) << 4);
            const uint32_t uB = (uint32_t)((((s << 1) | kbB) ^ r7) << 4);
            uint32_t b0[8], b1[8];
#pragma unroll
            for (int nip = 0; nip < 4; ++nip)
                LDSM_X4(b0[2*nip], b1[2*nip], b0[2*nip+1], b1[2*nip+1],
                        stage + bRow[nip] + uB);
#pragma unroll
            for (int mi = 0; mi < 4; ++mi) {
                uint32_t A0, A1, A2, A3;
                LDSM_X4(A0, A1, A2, A3, stage + aRow[mi] + uA);
#pragma unroll
                for (int ni = 0; ni < 8; ++ni)
                    mma_f16(acc[mi][ni], A0, A1, A2, A3, b0[ni], b1[ni]);
            }
        }
        __syncthreads();
    }

    // direct epilogue: r = mw*64+mi*16+half*8+lg -> i=by*4+(r>>5), c=r&31;
    // n = nw*64+ni*8+lm4*2 -> j = bx*4+nw*2+(ni>>2), d = (ni&3)*8+lm4*2.
#pragma unroll
    for (int mi = 0; mi < 4; ++mi) {
#pragma unroll
        for (int half = 0; half < 2; ++half) {
            const int r = mw * 64 + mi * 16 + half * 8 + lg;
            const int i = blockIdx.y * 4 + (r >> 5);
            const int c = r & 31;
#pragma unroll
            for (int ni = 0; ni < 8; ++ni) {
                const int j = blockIdx.x * 4 + nw * 2 + (ni >> 2);
                const int d = (ni & 3) * 8 + lm4 * 2;
                __half2 v = __floats2half2_rn(acc[mi][ni][half * 2 + 0],
                                              acc[mi][ni][half * 2 + 1]);
                __stcs((__half2*)(g_a + (size_t)(i * 384 + j) * 1024 + c * 32 + d), v);
            }
        }
    }
}

// ============================================================================
// gemm2: 128 thr, 4 warps 2x2, warp tile 64x64, fp16 m16n8k16.
// 128x128 tile, K=1024 in 16 chunks of 64; 2-stage ring; rmsnorm epilogue.
// ============================================================================
__global__ __launch_bounds__(128, 3)
void gemm2_kernel(const float* __restrict__ bo, const float* __restrict__ gout,
                  float* __restrict__ out) {
    extern __shared__ float sm[];
    const int tid = threadIdx.x, w = tid >> 5, l = tid & 31;
    const int mw = w >> 1, nw = w & 1, lg = l >> 2, lm4 = l & 3;
    const int p_base = blockIdx.x * 128;
    const uint32_t smb = smem_u32(sm);

    const int r7 = l & 7;
    const int rhiA = (l >> 3) & 1, kbA = (l >> 4) & 1;
    const int rhiB = (l >> 4) & 1, kbB = (l >> 3) & 1;
    uint32_t aRow[4], bRow[4];
#pragma unroll
    for (int mi = 0; mi < 4; ++mi)
        aRow[mi] = (uint32_t)((mw * 64 + mi * 16 + rhiA * 8 + r7) * 128);
#pragma unroll
    for (int nip = 0; nip < 4; ++nip)
        bRow[nip] = (uint32_t)(16384 + (nw * 64 + nip * 16 + rhiB * 8 + r7) * 128);

    float acc[4][8][4] = {};

    int srow[8], sq[8];
    uint32_t sdst[8];
#pragma unroll
    for (int v = 0; v < 8; ++v) {
        const int fl = v * 128 + tid;
        srow[v] = fl >> 3;
        sq[v]   = fl & 7;
        sdst[v] = (uint32_t)((srow[v] * 8 + (sq[v] ^ (srow[v] & 7))) * 16);
    }

#define G2_STAGE(ks, buf) do {                                                  \
    const uint32_t bofs = smb + (uint32_t)(buf) * 32768u;                       \
    _Pragma("unroll")                                                           \
    for (int v = 0; v < 8; ++v) {                                               \
        const __half* sA = g_a + (size_t)(p_base + srow[v]) * 1024 + (ks) * 64 + sq[v] * 8; \
        CP_ASYNC16(bofs + sdst[v], sA);                                         \
        const int fl = v * 128 + tid;                                           \
        const __half* sB = g_wo + (ks) * 8192 + fl * 8;                         \
        CP_ASYNC16(bofs + 16384 + (uint32_t)(fl * 16), sB);                     \
    }                                                                           \
    CP_COMMIT();                                                                \
} while (0)

    G2_STAGE(0, 0);
    for (int ks = 0; ks < 16; ++ks) {
        if (ks + 1 < 16) { G2_STAGE(ks + 1, (ks + 1) & 1); CP_WAIT1(); }
        else             { CP_WAIT0(); }
        __syncthreads();
        const uint32_t stage = smb + (uint32_t)(ks & 1) * 32768u;
#pragma unroll
        for (int s = 0; s < 4; ++s) {
            const uint32_t uA = (uint32_t)((((s << 1) | kbA) ^ r7) << 4);
            const uint32_t uB = (uint32_t)((((s << 1) | kbB) ^ r7) << 4);
            uint32_t b0[8], b1[8];
#pragma unroll
            for (int nip = 0; nip < 4; ++nip)
                LDSM_X4(b0[2*nip], b1[2*nip], b0[2*nip+1], b1[2*nip+1],
                        stage + bRow[nip] + uB);
#pragma unroll
            for (int mi = 0; mi < 4; ++mi) {
                uint32_t A0, A1, A2, A3;
                LDSM_X4(A0, A1, A2, A3, stage + aRow[mi] + uA);
#pragma unroll
                for (int ni = 0; ni < 8; ++ni)
                    mma_f16(acc[mi][ni], A0, A1, A2, A3, b0[ni], b1[ni]);
            }
        }
        __syncthreads();
    }

    // epilogue: acc -> Ds[128][132] -> bias + rmsnorm -> coalesced store
    float* Ds = sm;
#pragma unroll
    for (int mi = 0; mi < 4; ++mi) {
        const int r0 = mw * 64 + mi * 16 + lg;
#pragma unroll
        for (int ni = 0; ni < 8; ++ni) {
            const int c0 = nw * 64 + ni * 8 + lm4 * 2;
            *(float2*)(Ds + r0 * 132 + c0)       = make_float2(acc[mi][ni][0], acc[mi][ni][1]);
            *(float2*)(Ds + (r0 + 8) * 132 + c0) = make_float2(acc[mi][ni][2], acc[mi][ni][3]);
        }
    }
    __syncthreads();

    float* scA = sm + 16896;
    {
        float* rp = Ds + tid * 132;
        float ssq = 0.0f;
        for (int q = 0; q < 32; ++q) {
            float4 v = *(float4*)(rp + q * 4);
            const float4 bb = __ldg((const float4*)(bo + q * 4));
            v.x += bb.x; v.y += bb.y; v.z += bb.z; v.w += bb.w;
            ssq = fmaf(v.x, v.x, ssq);
            ssq = fmaf(v.y, v.y, ssq);
            ssq = fmaf(v.z, v.z, ssq);
            ssq = fmaf(v.w, v.w, ssq);
            *(float4*)(rp + q * 4) = v;
        }
        scA[tid] = rsqrtf(ssq * (1.0f / 128.0f) + EPSV);
    }
    __syncthreads();

#pragma unroll 4
    for (int v = 0; v < 32; ++v) {
        const int fl = v * 128 + tid;
        const int row = fl >> 5, col = (fl & 31) * 4;
        float4 vv = *(float4*)(Ds + row * 132 + col);
        const float sc = scA[row];
        const float4 gg = __ldg((const float4*)(gout + col));
        vv.x *= sc * gg.x; vv.y *= sc * gg.y;
        vv.z *= sc * gg.z; vv.w *= sc * gg.w;
        *(float4*)(out + (size_t)(p_base + row) * 128 + col) = vv;
    }
}

// ============================================================================
extern "C" void kernel_launch(void* const* d_in, const int* in_sizes, int n_in,
                              void* d_out, int out_size) {
    const float* m    = (const float*)d_in[0];
    const float* g_in = (const float*)d_in[1];
    const float* Wq   = (const float*)d_in[2];
    const float* bq   = (const float*)d_in[3];
    const float* Wk   = (const float*)d_in[4];
    const float* bk   = (const float*)d_in[5];
    const float* Wo   = (const float*)d_in[6];
    const float* bo   = (const float*)d_in[7];
    const float* gout = (const float*)d_in[8];
    float* out = (float*)d_out;

    cudaFuncSetAttribute(proj_kernel,  cudaFuncAttributeMaxDynamicSharedMemorySize, 98304);
    cudaFuncSetAttribute(gemm1_kernel, cudaFuncAttributeMaxDynamicSharedMemorySize, 65536);
    cudaFuncSetAttribute(gemm2_kernel, cudaFuncAttributeMaxDynamicSharedMemorySize, 69632);

    proj_kernel<<<(256 * 384) / 32, 256, 98304>>>(m, g_in, Wq, bq, Wk, bk);
    wot_kernel<<<16, 128>>>(Wo);
    gemm1_kernel<<<dim3(96, 96), 128, 65536>>>();
    gemm2_kernel<<<1152, 128, 69632>>>(bo, gout, out);
}

// round 13
// speedup vs baseline: 1.0858x; 1.0858x over previous
#include <cuda_runtime.h>
#include <cuda_fp16.h>
#include <cstdint>
#include <cstddef>

#define EPSV 1e-5f

// g_q/g_k: fp16 [(s*32+c)*256 + b] — GEMM1 operand rows, K(=b)-contiguous
__device__ __half g_q[384 * 32 * 256];
__device__ __half g_k[384 * 32 * 256];
// g_wo: fp16, 16 k-chunks, each preswizzled smem image [n=128][64 halfs]
__device__ __half g_wo[16 * 128 * 64];
// g_a: fp16 [p = i*384+j][e = c*32+d] row-major — GEMM2 A operand (302 MB)
__device__ __half g_a[150994944];

// ---------------- helpers ----------------
__device__ __forceinline__ uint32_t smem_u32(const void* p) {
    uint32_t a;
    asm("{ .reg .u64 t; cvta.to.shared.u64 t, %1; cvt.u32.u64 %0, t; }" : "=r"(a) : "l"(p));
    return a;
}
#define CP_ASYNC16(dst, src) \
    asm volatile("cp.async.cg.shared.global [%0], [%1], 16;" :: "r"(dst), "l"(src))
#define CP_COMMIT() asm volatile("cp.async.commit_group;")
#define CP_WAIT1()  asm volatile("cp.async.wait_group 1;")
#define CP_WAIT0()  asm volatile("cp.async.wait_group 0;")

#define LDSM_X4(r0, r1, r2, r3, addr) \
    asm volatile("ldmatrix.sync.aligned.m8n8.x4.shared.b16 {%0,%1,%2,%3}, [%4];" \
                 : "=r"(r0), "=r"(r1), "=r"(r2), "=r"(r3) : "r"(addr))

__device__ __forceinline__ void mma_f16(float* d, uint32_t a0, uint32_t a1,
                                        uint32_t a2, uint32_t a3,
                                        uint32_t b0, uint32_t b1) {
    asm volatile(
        "mma.sync.aligned.m16n8k16.row.col.f32.f16.f16.f32 "
        "{%0,%1,%2,%3}, {%4,%5,%6,%7}, {%8,%9}, {%0,%1,%2,%3};"
        : "+f"(d[0]), "+f"(d[1]), "+f"(d[2]), "+f"(d[3])
        : "r"(a0), "r"(a1), "r"(a2), "r"(a3), "r"(b0), "r"(b1));
}

// ============================================================================
// proj: rmsnorm(m)*g_in -> q/k projections -> fp16 transposed store
// ============================================================================
__global__ __launch_bounds__(256, 2)
void proj_kernel(const float* __restrict__ m, const float* __restrict__ g_in,
                 const float* __restrict__ Wq, const float* __restrict__ bq,
                 const float* __restrict__ Wk, const float* __restrict__ bk)
{
    extern __shared__ float sm[];
    float* Wq_s = sm;
    float* Wk_s = sm + 8192;
    float* mn_s = sm + 16384;
    const int tid = threadIdx.x, warp = tid >> 5, lane = tid & 31;
    const float4* Wq4 = (const float4*)Wq;
    const float4* Wk4 = (const float4*)Wk;
#pragma unroll
    for (int v = 0; v < 8; ++v) {
        ((float4*)Wq_s)[v * 256 + tid] = Wq4[v * 256 + tid];
        ((float4*)Wk_s)[v * 256 + tid] = Wk4[v * 256 + tid];
    }
    const int rb = (blockIdx.x * 8 + warp) * 4;
    float* mw = mn_s + warp * 1024;
    const float4 gi0 = ((const float4*)g_in)[lane * 2];
    const float4 gi1 = ((const float4*)g_in)[lane * 2 + 1];
    float vals[4][8], ssum[4];
#pragma unroll
    for (int r = 0; r < 4; ++r) {
        const float4* mp = (const float4*)(m + (size_t)(rb + r) * 256);
        float4 a = mp[lane * 2], b = mp[lane * 2 + 1];
        vals[r][0] = a.x; vals[r][1] = a.y; vals[r][2] = a.z; vals[r][3] = a.w;
        vals[r][4] = b.x; vals[r][5] = b.y; vals[r][6] = b.z; vals[r][7] = b.w;
        ssum[r] = a.x*a.x + a.y*a.y + a.z*a.z + a.w*a.w
                + b.x*b.x + b.y*b.y + b.z*b.z + b.w*b.w;
    }
#pragma unroll
    for (int r = 0; r < 4; ++r) {
        float s = ssum[r];
#pragma unroll
        for (int o = 16; o >= 1; o >>= 1) s += __shfl_xor_sync(~0u, s, o);
        const float sc = rsqrtf(s * (1.0f / 256.0f) + EPSV);
        float4 o0, o1;
        o0.x = vals[r][0]*sc*gi0.x; o0.y = vals[r][1]*sc*gi0.y;
        o0.z = vals[r][2]*sc*gi0.z; o0.w = vals[r][3]*sc*gi0.w;
        o1.x = vals[r][4]*sc*gi1.x; o1.y = vals[r][5]*sc*gi1.y;
        o1.z = vals[r][6]*sc*gi1.z; o1.w = vals[r][7]*sc*gi1.w;
        ((float4*)(mw + r * 256))[lane * 2]     = o0;
        ((float4*)(mw + r * 256))[lane * 2 + 1] = o1;
    }
    __syncthreads();
    float aq[4], ak[4];
    const float bqv = __ldg(bq + lane), bkv = __ldg(bk + lane);
#pragma unroll
    for (int r = 0; r < 4; ++r) { aq[r] = bqv; ak[r] = bkv; }
#pragma unroll 4
    for (int mm = 0; mm < 256; ++mm) {
        const float wq = Wq_s[mm * 32 + lane], wk = Wk_s[mm * 32 + lane];
#pragma unroll
        for (int r = 0; r < 4; ++r) {
            const float x = mw[r * 256 + mm];
            aq[r] = fmaf(x, wq, aq[r]);
            ak[r] = fmaf(x, wk, ak[r]);
        }
    }
#pragma unroll
    for (int r = 0; r < 4; ++r) {
        const int row = rb + r, b = row / 384, s = row - b * 384;
        g_q[(size_t)(s * 32 + lane) * 256 + b] = __float2half(aq[r]);
        g_k[(size_t)(s * 32 + lane) * 256 + b] = __float2half(ak[r]);
    }
}

// ============================================================================
// wot: Wo[e=ks*64+kk][z=n] -> g_wo[ks][n*64 + swz(kk,n)]  (fp16)
// ============================================================================
__global__ void wot_kernel(const float* __restrict__ Wo) {
    const int ks = blockIdx.x, n = threadIdx.x;
    __half* dst = g_wo + ks * 8192 + n * 64;
    const int n7 = n & 7;
#pragma unroll
    for (int kk = 0; kk < 64; ++kk) {
        const float v = __ldg(Wo + (size_t)(ks * 64 + kk) * 128 + n);
        dst[(((kk >> 3) ^ n7) << 3) | (kk & 7)] = __float2half(v);
    }
}

// ============================================================================
// gemm1 (R11 mainloop): 256 thr, 8 warps 2x4, warp tile 64x32, fp16 mma.
// 128x128 tile, K=256 in 4 chunks of 64; 3-stage ring.
// NEW epilogue: smem-staged Ds[128][132] -> coalesced 8B half stores.
// ============================================================================
__global__ __launch_bounds__(256, 2)
void gemm1_kernel() {
    extern __shared__ float sm[];
    const int tid = threadIdx.x, w = tid >> 5, l = tid & 31;
    const int mw = w >> 2, nw = w & 3, lg = l >> 2, lm4 = l & 3;
    const int irow = blockIdx.y * 128, jrow = blockIdx.x * 128;
    const uint32_t smb = smem_u32(sm);

    const int r7 = l & 7;
    const int rhiA = (l >> 3) & 1, kbA = (l >> 4) & 1;
    const int rhiB = (l >> 4) & 1, kbB = (l >> 3) & 1;
    uint32_t aRow[4], bRow[2];
#pragma unroll
    for (int mi = 0; mi < 4; ++mi)
        aRow[mi] = (uint32_t)((mw * 64 + mi * 16 + rhiA * 8 + r7) * 128);
#pragma unroll
    for (int nip = 0; nip < 2; ++nip)
        bRow[nip] = (uint32_t)(16384 + (nw * 32 + nip * 16 + rhiB * 8 + r7) * 128);

    float acc[4][4][4] = {};

    int srow[4], sq[4];
    uint32_t sdst[4];
#pragma unroll
    for (int v = 0; v < 4; ++v) {
        const int fl = v * 256 + tid;
        srow[v] = fl >> 3;
        sq[v]   = fl & 7;
        sdst[v] = (uint32_t)((srow[v] * 8 + (sq[v] ^ (srow[v] & 7))) * 16);
    }

#define G1_STAGE(ks, buf) do {                                                  \
    const uint32_t bofs = smb + (uint32_t)(buf) * 32768u;                       \
    _Pragma("unroll")                                                           \
    for (int v = 0; v < 4; ++v) {                                               \
        const __half* sA = g_q + (size_t)(irow + srow[v]) * 256 + (ks) * 64 + sq[v] * 8; \
        const __half* sB = g_k + (size_t)(jrow + srow[v]) * 256 + (ks) * 64 + sq[v] * 8; \
        CP_ASYNC16(bofs + sdst[v], sA);                                         \
        CP_ASYNC16(bofs + 16384 + sdst[v], sB);                                 \
    }                                                                           \
    CP_COMMIT();                                                                \
} while (0)

    G1_STAGE(0, 0);
    G1_STAGE(1, 1);
#pragma unroll
    for (int ks = 0; ks < 4; ++ks) {
        if (ks + 1 < 4) CP_WAIT1(); else CP_WAIT0();
        __syncthreads();
        if (ks + 2 < 4) G1_STAGE(ks + 2, (ks + 2) % 3);
        const uint32_t stage = smb + (uint32_t)(ks % 3) * 32768u;
#pragma unroll
        for (int s = 0; s < 4; ++s) {
            const uint32_t uA = (uint32_t)((((s << 1) | kbA) ^ r7) << 4);
            const uint32_t uB = (uint32_t)((((s << 1) | kbB) ^ r7) << 4);
            uint32_t b0[4], b1[4];
            LDSM_X4(b0[0], b1[0], b0[1], b1[1], stage + bRow[0] + uB);
            LDSM_X4(b0[2], b1[2], b0[3], b1[3], stage + bRow[1] + uB);
#pragma unroll
            for (int mi = 0; mi < 4; ++mi) {
                uint32_t A0, A1, A2, A3;
                LDSM_X4(A0, A1, A2, A3, stage + aRow[mi] + uA);
#pragma unroll
                for (int ni = 0; ni < 4; ++ni)
                    mma_f16(acc[mi][ni], A0, A1, A2, A3, b0[ni], b1[ni]);
            }
        }
    }
    __syncthreads();   // stage buffers free — reuse as Ds

    // stage D tile: Ds[128][132] float (proven conflict pattern)
    float* Ds = sm;
#pragma unroll
    for (int mi = 0; mi < 4; ++mi) {
        const int r0 = mw * 64 + mi * 16 + lg;
#pragma unroll
        for (int ni = 0; ni < 4; ++ni) {
            const int c0 = nw * 32 + ni * 8 + lm4 * 2;
            *(float2*)(Ds + r0 * 132 + c0)       = make_float2(acc[mi][ni][0], acc[mi][ni][1]);
            *(float2*)(Ds + (r0 + 8) * 132 + c0) = make_float2(acc[mi][ni][2], acc[mi][ni][3]);
        }
    }
    __syncthreads();

    // coalesced fp16 write-out: 16 threads per pair, 8B packed half2x2 stores
    const int pp = tid >> 4, t16 = tid & 15;
    const int ii = pp >> 2, jj = pp & 3;
    const int i = blockIdx.y * 4 + ii, j = blockIdx.x * 4 + jj;
    __half* dst = g_a + (size_t)(i * 384 + j) * 1024;
#pragma unroll
    for (int qq = 0; qq < 16; ++qq) {
        const int e = (t16 + qq * 16) * 4;
        const float* sp = Ds + (ii * 32 + (e >> 5)) * 132 + jj * 32 + (e & 31);
        float4 v = *(const float4*)sp;
        uint2 pk;
        __half2 h0 = __floats2half2_rn(v.x, v.y);
        __half2 h1 = __floats2half2_rn(v.z, v.w);
        pk.x = *(uint32_t*)&h0;
        pk.y = *(uint32_t*)&h1;
        __stcs((uint2*)(dst + e), pk);
    }
}

// ============================================================================
// gemm2: 128 thr, 4 warps 2x2, warp tile 64x64, fp16 m16n8k16.
// 128x128 tile, K=1024 in 16 chunks of 64; 2-stage ring; rmsnorm epilogue.
// ============================================================================
__global__ __launch_bounds__(128, 3)
void gemm2_kernel(const float* __restrict__ bo, const float* __restrict__ gout,
                  float* __restrict__ out) {
    extern __shared__ float sm[];
    const int tid = threadIdx.x, w = tid >> 5, l = tid & 31;
    const int mw = w >> 1, nw = w & 1, lg = l >> 2, lm4 = l & 3;
    const int p_base = blockIdx.x * 128;
    const uint32_t smb = smem_u32(sm);

    const int r7 = l & 7;
    const int rhiA = (l >> 3) & 1, kbA = (l >> 4) & 1;
    const int rhiB = (l >> 4) & 1, kbB = (l >> 3) & 1;
    uint32_t aRow[4], bRow[4];
#pragma unroll
    for (int mi = 0; mi < 4; ++mi)
        aRow[mi] = (uint32_t)((mw * 64 + mi * 16 + rhiA * 8 + r7) * 128);
#pragma unroll
    for (int nip = 0; nip < 4; ++nip)
        bRow[nip] = (uint32_t)(16384 + (nw * 64 + nip * 16 + rhiB * 8 + r7) * 128);

    float acc[4][8][4] = {};

    int srow[8], sq[8];
    uint32_t sdst[8];
#pragma unroll
    for (int v = 0; v < 8; ++v) {
        const int fl = v * 128 + tid;
        srow[v] = fl >> 3;
        sq[v]   = fl & 7;
        sdst[v] = (uint32_t)((srow[v] * 8 + (sq[v] ^ (srow[v] & 7))) * 16);
    }

#define G2_STAGE(ks, buf) do {                                                  \
    const uint32_t bofs = smb + (uint32_t)(buf) * 32768u;                       \
    _Pragma("unroll")                                                           \
    for (int v = 0; v < 8; ++v) {                                               \
        const __half* sA = g_a + (size_t)(p_base + srow[v]) * 1024 + (ks) * 64 + sq[v] * 8; \
        CP_ASYNC16(bofs + sdst[v], sA);                                         \
        const int fl = v * 128 + tid;                                           \
        const __half* sB = g_wo + (ks) * 8192 + fl * 8;                         \
        CP_ASYNC16(bofs + 16384 + (uint32_t)(fl * 16), sB);                     \
    }                                                                           \
    CP_COMMIT();                                                                \
} while (0)

    G2_STAGE(0, 0);
    for (int ks = 0; ks < 16; ++ks) {
        if (ks + 1 < 16) { G2_STAGE(ks + 1, (ks + 1) & 1); CP_WAIT1(); }
        else             { CP_WAIT0(); }
        __syncthreads();
        const uint32_t stage = smb + (uint32_t)(ks & 1) * 32768u;
#pragma unroll
        for (int s = 0; s < 4; ++s) {
            const uint32_t uA = (uint32_t)((((s << 1) | kbA) ^ r7) << 4);
            const uint32_t uB = (uint32_t)((((s << 1) | kbB) ^ r7) << 4);
            uint32_t b0[8], b1[8];
#pragma unroll
            for (int nip = 0; nip < 4; ++nip)
                LDSM_X4(b0[2*nip], b1[2*nip], b0[2*nip+1], b1[2*nip+1],
                        stage + bRow[nip] + uB);
#pragma unroll
            for (int mi = 0; mi < 4; ++mi) {
                uint32_t A0, A1, A2, A3;
                LDSM_X4(A0, A1, A2, A3, stage + aRow[mi] + uA);
#pragma unroll
                for (int ni = 0; ni < 8; ++ni)
                    mma_f16(acc[mi][ni], A0, A1, A2, A3, b0[ni], b1[ni]);
            }
        }
        __syncthreads();
    }

    // epilogue: acc -> Ds[128][132] -> bias + rmsnorm -> coalesced store
    float* Ds = sm;
#pragma unroll
    for (int mi = 0; mi < 4; ++mi) {
        const int r0 = mw * 64 + mi * 16 + lg;
#pragma unroll
        for (int ni = 0; ni < 8; ++ni) {
            const int c0 = nw * 64 + ni * 8 + lm4 * 2;
            *(float2*)(Ds + r0 * 132 + c0)       = make_float2(acc[mi][ni][0], acc[mi][ni][1]);
            *(float2*)(Ds + (r0 + 8) * 132 + c0) = make_float2(acc[mi][ni][2], acc[mi][ni][3]);
        }
    }
    __syncthreads();

    float* scA = sm + 16896;
    {
        float* rp = Ds + tid * 132;
        float ssq = 0.0f;
        for (int q = 0; q < 32; ++q) {
            float4 v = *(float4*)(rp + q * 4);
            const float4 bb = __ldg((const float4*)(bo + q * 4));
            v.x += bb.x; v.y += bb.y; v.z += bb.z; v.w += bb.w;
            ssq = fmaf(v.x, v.x, ssq);
            ssq = fmaf(v.y, v.y, ssq);
            ssq = fmaf(v.z, v.z, ssq);
            ssq = fmaf(v.w, v.w, ssq);
            *(float4*)(rp + q * 4) = v;
        }
        scA[tid] = rsqrtf(ssq * (1.0f / 128.0f) + EPSV);
    }
    __syncthreads();

#pragma unroll 4
    for (int v = 0; v < 32; ++v) {
        const int fl = v * 128 + tid;
        const int row = fl >> 5, col = (fl & 31) * 4;
        float4 vv = *(float4*)(Ds + row * 132 + col);
        const float sc = scA[row];
        const float4 gg = __ldg((const float4*)(gout + col));
        vv.x *= sc * gg.x; vv.y *= sc * gg.y;
        vv.z *= sc * gg.z; vv.w *= sc * gg.w;
        *(float4*)(out + (size_t)(p_base + row) * 128 + col) = vv;
    }
}

// ============================================================================
extern "C" void kernel_launch(void* const* d_in, const int* in_sizes, int n_in,
                              void* d_out, int out_size) {
    const float* m    = (const float*)d_in[0];
    const float* g_in = (const float*)d_in[1];
    const float* Wq   = (const float*)d_in[2];
    const float* bq   = (const float*)d_in[3];
    const float* Wk   = (const float*)d_in[4];
    const float* bk   = (const float*)d_in[5];
    const float* Wo   = (const float*)d_in[6];
    const float* bo   = (const float*)d_in[7];
    const float* gout = (const float*)d_in[8];
    float* out = (float*)d_out;

    cudaFuncSetAttribute(proj_kernel,  cudaFuncAttributeMaxDynamicSharedMemorySize, 98304);
    cudaFuncSetAttribute(gemm1_kernel, cudaFuncAttributeMaxDynamicSharedMemorySize, 98304);
    cudaFuncSetAttribute(gemm2_kernel, cudaFuncAttributeMaxDynamicSharedMemorySize, 69632);

    proj_kernel<<<(256 * 384) / 32, 256, 98304>>>(m, g_in, Wq, bq, Wk, bk);
    wot_kernel<<<16, 128>>>(Wo);
    gemm1_kernel<<<dim3(96, 96), 256, 98304>>>();
    gemm2_kernel<<<1152, 128, 69632>>>(bo, gout, out);
}

// round 14
// speedup vs baseline: 1.1929x; 1.0986x over previous
#include <cuda_runtime.h>
#include <cuda_fp16.h>
#include <cstdint>
#include <cstddef>

#define EPSV 1e-5f

// g_q/g_k: fp16 [(s*32+c)*256 + b] — GEMM1 operand rows, K(=b)-contiguous
__device__ __half g_q[384 * 32 * 256];
__device__ __half g_k[384 * 32 * 256];
// g_wo: fp16, 16 k-chunks, each preswizzled smem image [n=128][64 halfs]
__device__ __half g_wo[16 * 128 * 64];
// g_a: fp16 [p = i*384+j][e = c*32+d] row-major — GEMM2 A operand (302 MB)
__device__ __half g_a[150994944];

// ---------------- helpers ----------------
__device__ __forceinline__ uint32_t smem_u32(const void* p) {
    uint32_t a;
    asm("{ .reg .u64 t; cvta.to.shared.u64 t, %1; cvt.u32.u64 %0, t; }" : "=r"(a) : "l"(p));
    return a;
}
#define CP_ASYNC16(dst, src) \
    asm volatile("cp.async.cg.shared.global [%0], [%1], 16;" :: "r"(dst), "l"(src))
#define CP_COMMIT() asm volatile("cp.async.commit_group;")
#define CP_WAIT1()  asm volatile("cp.async.wait_group 1;")
#define CP_WAIT0()  asm volatile("cp.async.wait_group 0;")

#define LDSM_X4(r0, r1, r2, r3, addr) \
    asm volatile("ldmatrix.sync.aligned.m8n8.x4.shared.b16 {%0,%1,%2,%3}, [%4];" \
                 : "=r"(r0), "=r"(r1), "=r"(r2), "=r"(r3) : "r"(addr))

__device__ __forceinline__ void mma_f16(float* d, uint32_t a0, uint32_t a1,
                                        uint32_t a2, uint32_t a3,
                                        uint32_t b0, uint32_t b1) {
    asm volatile(
        "mma.sync.aligned.m16n8k16.row.col.f32.f16.f16.f32 "
        "{%0,%1,%2,%3}, {%4,%5,%6,%7}, {%8,%9}, {%0,%1,%2,%3};"
        : "+f"(d[0]), "+f"(d[1]), "+f"(d[2]), "+f"(d[3])
        : "r"(a0), "r"(a1), "r"(a2), "r"(a3), "r"(b0), "r"(b1));
}

// ============================================================================
// proj: rmsnorm(m)*g_in -> q/k projections -> fp16 transposed store
// ============================================================================
__global__ __launch_bounds__(256, 2)
void proj_kernel(const float* __restrict__ m, const float* __restrict__ g_in,
                 const float* __restrict__ Wq, const float* __restrict__ bq,
                 const float* __restrict__ Wk, const float* __restrict__ bk)
{
    extern __shared__ float sm[];
    float* Wq_s = sm;
    float* Wk_s = sm + 8192;
    float* mn_s = sm + 16384;
    const int tid = threadIdx.x, warp = tid >> 5, lane = tid & 31;
    const float4* Wq4 = (const float4*)Wq;
    const float4* Wk4 = (const float4*)Wk;
#pragma unroll
    for (int v = 0; v < 8; ++v) {
        ((float4*)Wq_s)[v * 256 + tid] = Wq4[v * 256 + tid];
        ((float4*)Wk_s)[v * 256 + tid] = Wk4[v * 256 + tid];
    }
    const int rb = (blockIdx.x * 8 + warp) * 4;
    float* mw = mn_s + warp * 1024;
    const float4 gi0 = ((const float4*)g_in)[lane * 2];
    const float4 gi1 = ((const float4*)g_in)[lane * 2 + 1];
    float vals[4][8], ssum[4];
#pragma unroll
    for (int r = 0; r < 4; ++r) {
        const float4* mp = (const float4*)(m + (size_t)(rb + r) * 256);
        float4 a = mp[lane * 2], b = mp[lane * 2 + 1];
        vals[r][0] = a.x; vals[r][1] = a.y; vals[r][2] = a.z; vals[r][3] = a.w;
        vals[r][4] = b.x; vals[r][5] = b.y; vals[r][6] = b.z; vals[r][7] = b.w;
        ssum[r] = a.x*a.x + a.y*a.y + a.z*a.z + a.w*a.w
                + b.x*b.x + b.y*b.y + b.z*b.z + b.w*b.w;
    }
#pragma unroll
    for (int r = 0; r < 4; ++r) {
        float s = ssum[r];
#pragma unroll
        for (int o = 16; o >= 1; o >>= 1) s += __shfl_xor_sync(~0u, s, o);
        const float sc = rsqrtf(s * (1.0f / 256.0f) + EPSV);
        float4 o0, o1;
        o0.x = vals[r][0]*sc*gi0.x; o0.y = vals[r][1]*sc*gi0.y;
        o0.z = vals[r][2]*sc*gi0.z; o0.w = vals[r][3]*sc*gi0.w;
        o1.x = vals[r][4]*sc*gi1.x; o1.y = vals[r][5]*sc*gi1.y;
        o1.z = vals[r][6]*sc*gi1.z; o1.w = vals[r][7]*sc*gi1.w;
        ((float4*)(mw + r * 256))[lane * 2]     = o0;
        ((float4*)(mw + r * 256))[lane * 2 + 1] = o1;
    }
    __syncthreads();
    float aq[4], ak[4];
    const float bqv = __ldg(bq + lane), bkv = __ldg(bk + lane);
#pragma unroll
    for (int r = 0; r < 4; ++r) { aq[r] = bqv; ak[r] = bkv; }
#pragma unroll 4
    for (int mm = 0; mm < 256; ++mm) {
        const float wq = Wq_s[mm * 32 + lane], wk = Wk_s[mm * 32 + lane];
#pragma unroll
        for (int r = 0; r < 4; ++r) {
            const float x = mw[r * 256 + mm];
            aq[r] = fmaf(x, wq, aq[r]);
            ak[r] = fmaf(x, wk, ak[r]);
        }
    }
#pragma unroll
    for (int r = 0; r < 4; ++r) {
        const int row = rb + r, b = row / 384, s = row - b * 384;
        g_q[(size_t)(s * 32 + lane) * 256 + b] = __float2half(aq[r]);
        g_k[(size_t)(s * 32 + lane) * 256 + b] = __float2half(ak[r]);
    }
}

// ============================================================================
// wot: Wo[e=ks*64+kk][z=n] -> g_wo[ks][n*64 + swz(kk,n)]  (fp16)
// ============================================================================
__global__ void wot_kernel(const float* __restrict__ Wo) {
    const int ks = blockIdx.x, n = threadIdx.x;
    __half* dst = g_wo + ks * 8192 + n * 64;
    const int n7 = n & 7;
#pragma unroll
    for (int kk = 0; kk < 64; ++kk) {
        const float v = __ldg(Wo + (size_t)(ks * 64 + kk) * 128 + n);
        dst[(((kk >> 3) ^ n7) << 3) | (kk & 7)] = __float2half(v);
    }
}

// ============================================================================
// gemm1 (R11 champion): 256 thr, 8 warps 2x4, warp tile 64x32, fp16 mma.
// 128x128 tile, K=256 in 4 chunks of 64; 3-stage ring; direct scatter.
// ============================================================================
__global__ __launch_bounds__(256, 2)
void gemm1_kernel() {
    extern __shared__ float sm[];
    const int tid = threadIdx.x, w = tid >> 5, l = tid & 31;
    const int mw = w >> 2, nw = w & 3, lg = l >> 2, lm4 = l & 3;
    const int irow = blockIdx.y * 128, jrow = blockIdx.x * 128;
    const uint32_t smb = smem_u32(sm);

    const int r7 = l & 7;
    const int rhiA = (l >> 3) & 1, kbA = (l >> 4) & 1;
    const int rhiB = (l >> 4) & 1, kbB = (l >> 3) & 1;
    uint32_t aRow[4], bRow[2];
#pragma unroll
    for (int mi = 0; mi < 4; ++mi)
        aRow[mi] = (uint32_t)((mw * 64 + mi * 16 + rhiA * 8 + r7) * 128);
#pragma unroll
    for (int nip = 0; nip < 2; ++nip)
        bRow[nip] = (uint32_t)(16384 + (nw * 32 + nip * 16 + rhiB * 8 + r7) * 128);

    float acc[4][4][4] = {};

    int srow[4], sq[4];
    uint32_t sdst[4];
#pragma unroll
    for (int v = 0; v < 4; ++v) {
        const int fl = v * 256 + tid;
        srow[v] = fl >> 3;
        sq[v]   = fl & 7;
        sdst[v] = (uint32_t)((srow[v] * 8 + (sq[v] ^ (srow[v] & 7))) * 16);
    }

#define G1_STAGE(ks, buf) do {                                                  \
    const uint32_t bofs = smb + (uint32_t)(buf) * 32768u;                       \
    _Pragma("unroll")                                                           \
    for (int v = 0; v < 4; ++v) {                                               \
        const __half* sA = g_q + (size_t)(irow + srow[v]) * 256 + (ks) * 64 + sq[v] * 8; \
        const __half* sB = g_k + (size_t)(jrow + srow[v]) * 256 + (ks) * 64 + sq[v] * 8; \
        CP_ASYNC16(bofs + sdst[v], sA);                                         \
        CP_ASYNC16(bofs + 16384 + sdst[v], sB);                                 \
    }                                                                           \
    CP_COMMIT();                                                                \
} while (0)

    G1_STAGE(0, 0);
    G1_STAGE(1, 1);
#pragma unroll
    for (int ks = 0; ks < 4; ++ks) {
        if (ks + 1 < 4) CP_WAIT1(); else CP_WAIT0();
        __syncthreads();
        if (ks + 2 < 4) G1_STAGE(ks + 2, (ks + 2) % 3);
        const uint32_t stage = smb + (uint32_t)(ks % 3) * 32768u;
#pragma unroll
        for (int s = 0; s < 4; ++s) {
            const uint32_t uA = (uint32_t)((((s << 1) | kbA) ^ r7) << 4);
            const uint32_t uB = (uint32_t)((((s << 1) | kbB) ^ r7) << 4);
            uint32_t b0[4], b1[4];
            LDSM_X4(b0[0], b1[0], b0[1], b1[1], stage + bRow[0] + uB);
            LDSM_X4(b0[2], b1[2], b0[3], b1[3], stage + bRow[1] + uB);
#pragma unroll
            for (int mi = 0; mi < 4; ++mi) {
                uint32_t A0, A1, A2, A3;
                LDSM_X4(A0, A1, A2, A3, stage + aRow[mi] + uA);
#pragma unroll
                for (int ni = 0; ni < 4; ++ni)
                    mma_f16(acc[mi][ni], A0, A1, A2, A3, b0[ni], b1[ni]);
            }
        }
    }

    // direct epilogue: fp16 half2 scatter into g_a
    const int j = blockIdx.x * 4 + nw;
#pragma unroll
    for (int mi = 0; mi < 4; ++mi) {
        const int r_lo = mw * 64 + mi * 16 + lg;
#pragma unroll
        for (int half = 0; half < 2; ++half) {
            const int r = r_lo + half * 8;
            const int i = blockIdx.y * 4 + (r >> 5);
            const int c = r & 31;
            __half* base = g_a + (size_t)(i * 384 + j) * 1024 + c * 32 + lm4 * 2;
#pragma unroll
            for (int ni = 0; ni < 4; ++ni) {
                __half2 v = __floats2half2_rn(acc[mi][ni][half * 2 + 0],
                                              acc[mi][ni][half * 2 + 1]);
                __stcs((__half2*)(base + ni * 8), v);
            }
        }
    }
}

// ============================================================================
// gemm2: 128 thr, 4 warps 2x2, warp tile 64x64, fp16 m16n8k16.
// 128x128 tile, K=1024 in 16 chunks of 64; 2-stage ring; rmsnorm epilogue.
// ============================================================================
__global__ __launch_bounds__(128, 3)
void gemm2_kernel(const float* __restrict__ bo, const float* __restrict__ gout,
                  float* __restrict__ out) {
    extern __shared__ float sm[];
    const int tid = threadIdx.x, w = tid >> 5, l = tid & 31;
    const int mw = w >> 1, nw = w & 1, lg = l >> 2, lm4 = l & 3;
    const int p_base = blockIdx.x * 128;
    const uint32_t smb = smem_u32(sm);

    const int r7 = l & 7;
    const int rhiA = (l >> 3) & 1, kbA = (l >> 4) & 1;
    const int rhiB = (l >> 4) & 1, kbB = (l >> 3) & 1;
    uint32_t aRow[4], bRow[4];
#pragma unroll
    for (int mi = 0; mi < 4; ++mi)
        aRow[mi] = (uint32_t)((mw * 64 + mi * 16 + rhiA * 8 + r7) * 128);
#pragma unroll
    for (int nip = 0; nip < 4; ++nip)
        bRow[nip] = (uint32_t)(16384 + (nw * 64 + nip * 16 + rhiB * 8 + r7) * 128);

    float acc[4][8][4] = {};

    int srow[8], sq[8];
    uint32_t sdst[8];
#pragma unroll
    for (int v = 0; v < 8; ++v) {
        const int fl = v * 128 + tid;
        srow[v] = fl >> 3;
        sq[v]   = fl & 7;
        sdst[v] = (uint32_t)((srow[v] * 8 + (sq[v] ^ (srow[v] & 7))) * 16);
    }

#define G2_STAGE(ks, buf) do {                                                  \
    const uint32_t bofs = smb + (uint32_t)(buf) * 32768u;                       \
    _Pragma("unroll")                                                           \
    for (int v = 0; v < 8; ++v) {                                               \
        const __half* sA = g_a + (size_t)(p_base + srow[v]) * 1024 + (ks) * 64 + sq[v] * 8; \
        CP_ASYNC16(bofs + sdst[v], sA);                                         \
        const int fl = v * 128 + tid;                                           \
        const __half* sB = g_wo + (ks) * 8192 + fl * 8;                         \
        CP_ASYNC16(bofs + 16384 + (uint32_t)(fl * 16), sB);                     \
    }                                                                           \
    CP_COMMIT();                                                                \
} while (0)

    G2_STAGE(0, 0);
    for (int ks = 0; ks < 16; ++ks) {
        if (ks + 1 < 16) { G2_STAGE(ks + 1, (ks + 1) & 1); CP_WAIT1(); }
        else             { CP_WAIT0(); }
        __syncthreads();
        const uint32_t stage = smb + (uint32_t)(ks & 1) * 32768u;
#pragma unroll
        for (int s = 0; s < 4; ++s) {
            const uint32_t uA = (uint32_t)((((s << 1) | kbA) ^ r7) << 4);
            const uint32_t uB = (uint32_t)((((s << 1) | kbB) ^ r7) << 4);
            uint32_t b0[8], b1[8];
#pragma unroll
            for (int nip = 0; nip < 4; ++nip)
                LDSM_X4(b0[2*nip], b1[2*nip], b0[2*nip+1], b1[2*nip+1],
                        stage + bRow[nip] + uB);
#pragma unroll
            for (int mi = 0; mi < 4; ++mi) {
                uint32_t A0, A1, A2, A3;
                LDSM_X4(A0, A1, A2, A3, stage + aRow[mi] + uA);
#pragma unroll
                for (int ni = 0; ni < 8; ++ni)
                    mma_f16(acc[mi][ni], A0, A1, A2, A3, b0[ni], b1[ni]);
            }
        }
        __syncthreads();
    }

    // epilogue: acc -> Ds[128][132] -> bias + rmsnorm -> coalesced store
    float* Ds = sm;
#pragma unroll
    for (int mi = 0; mi < 4; ++mi) {
        const int r0 = mw * 64 + mi * 16 + lg;
#pragma unroll
        for (int ni = 0; ni < 8; ++ni) {
            const int c0 = nw * 64 + ni * 8 + lm4 * 2;
            *(float2*)(Ds + r0 * 132 + c0)       = make_float2(acc[mi][ni][0], acc[mi][ni][1]);
            *(float2*)(Ds + (r0 + 8) * 132 + c0) = make_float2(acc[mi][ni][2], acc[mi][ni][3]);
        }
    }
    __syncthreads();

    float* scA = sm + 16896;
    {
        float* rp = Ds + tid * 132;
        float ssq = 0.0f;
        for (int q = 0; q < 32; ++q) {
            float4 v = *(float4*)(rp + q * 4);
            const float4 bb = __ldg((const float4*)(bo + q * 4));
            v.x += bb.x; v.y += bb.y; v.z += bb.z; v.w += bb.w;
            ssq = fmaf(v.x, v.x, ssq);
            ssq = fmaf(v.y, v.y, ssq);
            ssq = fmaf(v.z, v.z, ssq);
            ssq = fmaf(v.w, v.w, ssq);
            *(float4*)(rp + q * 4) = v;
        }
        scA[tid] = rsqrtf(ssq * (1.0f / 128.0f) + EPSV);
    }
    __syncthreads();

#pragma unroll 4
    for (int v = 0; v < 32; ++v) {
        const int fl = v * 128 + tid;
        const int row = fl >> 5, col = (fl & 31) * 4;
        float4 vv = *(float4*)(Ds + row * 132 + col);
        const float sc = scA[row];
        const float4 gg = __ldg((const float4*)(gout + col));
        vv.x *= sc * gg.x; vv.y *= sc * gg.y;
        vv.z *= sc * gg.z; vv.w *= sc * gg.w;
        *(float4*)(out + (size_t)(p_base + row) * 128 + col) = vv;
    }
}

// ============================================================================
extern "C" void kernel_launch(void* const* d_in, const int* in_sizes, int n_in,
                              void* d_out, int out_size) {
    const float* m    = (const float*)d_in[0];
    const float* g_in = (const float*)d_in[1];
    const float* Wq   = (const float*)d_in[2];
    const float* bq   = (const float*)d_in[3];
    const float* Wk   = (const float*)d_in[4];
    const float* bk   = (const float*)d_in[5];
    const float* Wo   = (const float*)d_in[6];
    const float* bo   = (const float*)d_in[7];
    const float* gout = (const float*)d_in[8];
    float* out = (float*)d_out;

    cudaFuncSetAttribute(proj_kernel,  cudaFuncAttributeMaxDynamicSharedMemorySize, 98304);
    cudaFuncSetAttribute(gemm1_kernel, cudaFuncAttributeMaxDynamicSharedMemorySize, 98304);
    cudaFuncSetAttribute(gemm2_kernel, cudaFuncAttributeMaxDynamicSharedMemorySize, 69632);

    proj_kernel<<<(256 * 384) / 32, 256, 98304>>>(m, g_in, Wq, bq, Wk, bk);
    wot_kernel<<<16, 128>>>(Wo);
    gemm1_kernel<<<dim3(96, 96), 256, 98304>>>();
    gemm2_kernel<<<1152, 128, 69632>>>(bo, gout, out);
}